// round 11
// baseline (speedup 1.0000x reference)
#include <cuda_runtime.h>
#include <math.h>
#include <float.h>

#define D_MODEL 1024
#define NUM_HEADS 16
#define D_K 64
#define SEQ 2048
#define BATCH 4

// Scratch (static device globals -- no runtime allocation allowed)
__device__ float g_q[BATCH * SEQ * D_MODEL];
__device__ float g_k[BATCH * SEQ * D_MODEL];
__device__ float g_v[BATCH * SEQ * D_MODEL];
__device__ float g_attn[BATCH * SEQ * D_MODEL];

// ---------------------------------------------------------------------------
// tf32 helpers
// ---------------------------------------------------------------------------
__device__ __forceinline__ unsigned f2tf(float x) {
    unsigned u;
    asm("cvt.rna.tf32.f32 %0, %1;" : "=r"(u) : "f"(x));
    return u;
}

__device__ __forceinline__ uint4 cvt4(float4 v) {
    return make_uint4(f2tf(v.x), f2tf(v.y), f2tf(v.z), f2tf(v.w));
}

__device__ __forceinline__ void mma_tf32(float c[4], const unsigned a[4],
                                         unsigned b0, unsigned b1) {
    asm volatile(
        "mma.sync.aligned.m16n8k8.row.col.f32.tf32.tf32.f32 "
        "{%0,%1,%2,%3}, {%4,%5,%6,%7}, {%8,%9}, {%0,%1,%2,%3};\n"
        : "+f"(c[0]), "+f"(c[1]), "+f"(c[2]), "+f"(c[3])
        : "r"(a[0]), "r"(a[1]), "r"(a[2]), "r"(a[3]), "r"(b0), "r"(b1));
}

// ---------------------------------------------------------------------------
// TF32 tensor-core GEMM with fused bias + register-prefetch pipeline.
// C[M,N] = A[M,K] @ Bz[K,N] + biasz[N], operand set selected by blockIdx.z.
// BM=128, BN=128, BK=32. 512 threads = 16 warps (4m x 4n), warp tile 32x32.
// Per iter: STS(prefetched regs) -> bar -> LDG next tile (hidden behind MMAs)
// -> 32 MMAs/warp -> bar.  cvt.rna once per element at STS time.
// As: m-major [128][36]; Bs: k-major [32][136]; conflict-free frag loads.
// ---------------------------------------------------------------------------
#define GA_STR 36
#define GB_STR 136

__global__ __launch_bounds__(512) void gemm_tc(
    const float* __restrict__ A,
    const float* __restrict__ B0, const float* __restrict__ B1,
    const float* __restrict__ B2,
    const float* __restrict__ bias0, const float* __restrict__ bias1,
    const float* __restrict__ bias2,
    float* __restrict__ C0, float* __restrict__ C1, float* __restrict__ C2,
    int M, int N, int K)
{
    __shared__ unsigned As[128 * GA_STR];
    __shared__ unsigned Bs[32 * GB_STR];

    int z = blockIdx.z;
    const float* B    = (z == 0) ? B0    : (z == 1) ? B1    : B2;
    const float* bias = (z == 0) ? bias0 : (z == 1) ? bias1 : bias2;
    float*       C    = (z == 0) ? C0    : (z == 1) ? C1    : C2;

    int t    = threadIdx.x;
    int lane = t & 31;
    int w    = t >> 5;         // 0..15
    int wm   = w >> 2;         // 0..3
    int wn   = w & 3;          // 0..3
    int bm   = blockIdx.y * 128;
    int bn   = blockIdx.x * 128;
    int lq   = lane >> 2;      // 0..7
    int lr4  = lane & 3;       // 0..3

    // loader indices: 8 floats of A + 8 floats of B per thread per BK tile
    int am = t >> 2;           // 0..127
    int ak = (t & 3) * 8;      // 0,8,16,24
    int br = t >> 4;           // 0..31
    int bc = (t & 15) * 8;     // 0..120

    float acc[2][4][4];
    #pragma unroll
    for (int mt = 0; mt < 2; mt++)
        #pragma unroll
        for (int nt = 0; nt < 4; nt++)
            #pragma unroll
            for (int i = 0; i < 4; i++) acc[mt][nt][i] = 0.f;

    // prefetch tile 0 into registers
    float4 pa0, pa1, pb0, pb1;
    {
        const float* Ag = &A[(size_t)(bm + am) * K + ak];
        pa0 = *(const float4*)Ag;
        pa1 = *(const float4*)(Ag + 4);
        const float* Bg = &B[(size_t)br * N + bn + bc];
        pb0 = *(const float4*)Bg;
        pb1 = *(const float4*)(Bg + 4);
    }

    for (int kb = 0; kb < K; kb += 32) {
        // publish prefetched tile (cvt at store; 1x per element)
        *(uint4*)&As[am * GA_STR + ak]     = cvt4(pa0);
        *(uint4*)&As[am * GA_STR + ak + 4] = cvt4(pa1);
        *(uint4*)&Bs[br * GB_STR + bc]     = cvt4(pb0);
        *(uint4*)&Bs[br * GB_STR + bc + 4] = cvt4(pb1);
        __syncthreads();

        // issue next-tile LDGs; latency hidden behind the MMA block below
        if (kb + 32 < K) {
            const float* Ag = &A[(size_t)(bm + am) * K + kb + 32 + ak];
            pa0 = *(const float4*)Ag;
            pa1 = *(const float4*)(Ag + 4);
            const float* Bg = &B[(size_t)(kb + 32 + br) * N + bn + bc];
            pb0 = *(const float4*)Bg;
            pb1 = *(const float4*)(Bg + 4);
        }

        #pragma unroll
        for (int k8 = 0; k8 < 4; k8++) {
            int kc = k8 * 8 + lr4;
            unsigned a[2][4];
            #pragma unroll
            for (int mt = 0; mt < 2; mt++) {
                int mr = wm * 32 + mt * 16 + lq;
                a[mt][0] = As[mr * GA_STR + kc];
                a[mt][1] = As[(mr + 8) * GA_STR + kc];
                a[mt][2] = As[mr * GA_STR + kc + 4];
                a[mt][3] = As[(mr + 8) * GA_STR + kc + 4];
            }
            unsigned b[4][2];
            #pragma unroll
            for (int nt = 0; nt < 4; nt++) {
                int nc = wn * 32 + nt * 8 + lq;
                b[nt][0] = Bs[kc * GB_STR + nc];
                b[nt][1] = Bs[(kc + 4) * GB_STR + nc];
            }
            #pragma unroll
            for (int mt = 0; mt < 2; mt++)
                #pragma unroll
                for (int nt = 0; nt < 4; nt++)
                    mma_tf32(acc[mt][nt], a[mt], b[nt][0], b[nt][1]);
        }
        __syncthreads();
    }

    // epilogue
    #pragma unroll
    for (int nt = 0; nt < 4; nt++) {
        int col = bn + wn * 32 + nt * 8 + 2 * lr4;
        float2 bi = *(const float2*)&bias[col];
        #pragma unroll
        for (int mt = 0; mt < 2; mt++) {
            int r0 = bm + wm * 32 + mt * 16 + lq;
            float2 o0 = make_float2(acc[mt][nt][0] + bi.x, acc[mt][nt][1] + bi.y);
            float2 o1 = make_float2(acc[mt][nt][2] + bi.x, acc[mt][nt][3] + bi.y);
            *(float2*)&C[(size_t)r0 * N + col] = o0;
            *(float2*)&C[(size_t)(r0 + 8) * N + col] = o1;
        }
    }
}

// ---------------------------------------------------------------------------
// TF32 tensor-core causal flash attention, 128q x 64k tiles (R6-proven).
// 256 threads = 8 warps; warp w owns rows w*16..w*16+15 and ALL 64 keys.
// S stays in registers through softmax (row reductions = 2 shfl over lr4).
// P relayout to A-fragment via warp-private smem region (syncwarp only).
// Smem (floats): Qs[128][68], Ks[64][72] (d-major), Vs[64][72], Ps[128][68].
// ---------------------------------------------------------------------------
#define FQ_STR 68
#define FK_STR 72
#define FA_SMEM ((128 * FQ_STR + 64 * FK_STR * 2 + 128 * FQ_STR) * 4)

__global__ __launch_bounds__(256, 2) void flash_attn_tc(
    const float* __restrict__ Q, const float* __restrict__ K,
    const float* __restrict__ V, float* __restrict__ O)
{
    extern __shared__ unsigned usm[];
    unsigned* Qs  = usm;                         // 128*68  (tf32, pre-scaled)
    unsigned* Ks  = Qs + 128 * FQ_STR;           // 64*72   [d][key]
    unsigned* Vsm = Ks + 64 * FK_STR;            // 64*72   [key][d]
    unsigned* Ps  = Vsm + 64 * FK_STR;           // 128*68  (tf32 P)

    int bh = blockIdx.x;                  // 0..63
    int qt = 15 - blockIdx.y;             // long blocks first
    int b  = bh >> 4;
    int h  = bh & 15;
    int qb = qt * 128;

    const float* Qbase = Q + (size_t)b * SEQ * D_MODEL + h * D_K;
    const float* Kbase = K + (size_t)b * SEQ * D_MODEL + h * D_K;
    const float* Vbase = V + (size_t)b * SEQ * D_MODEL + h * D_K;
    float*       Obase = O + (size_t)b * SEQ * D_MODEL + h * D_K;

    int t    = threadIdx.x;
    int lane = t & 31;
    int w    = t >> 5;         // warp 0..7 -> rows w*16..+15
    int lq   = lane >> 2;      // 0..7
    int lr4  = lane & 3;       // 0..3
    int rw   = w * 16 + lq;    // warp-local row (first half)

    // ---- load Q tile (128x64) as tf32, scale folded ----
    {
        int lr  = t >> 4;          // 0..15
        int ld4 = (t & 15) * 4;
        #pragma unroll
        for (int c = 0; c < 8; c++) {
            int r = lr + c * 16;
            float4 q4 = *(const float4*)&Qbase[(size_t)(qb + r) * D_MODEL + ld4];
            uint4 u = make_uint4(f2tf(q4.x * 0.125f), f2tf(q4.y * 0.125f),
                                 f2tf(q4.z * 0.125f), f2tf(q4.w * 0.125f));
            *(uint4*)&Qs[r * FQ_STR + ld4] = u;
        }
    }

    float o[8][4];
    #pragma unroll
    for (int nt = 0; nt < 8; nt++)
        #pragma unroll
        for (int i = 0; i < 4; i++) o[nt][i] = 0.f;

    float m0 = -FLT_MAX, m1 = -FLT_MAX, l0 = 0.f, l1 = 0.f;

    int kr = t & 63;           // K loader: row 0..63
    int kg = t >> 6;           // d-group 0..3
    int lr = t >> 4;           // V loader row base
    int ld4 = (t & 15) * 4;

    int nkt = 2 * qt + 2;
    for (int kt = 0; kt < nkt; kt++) {
        int kb = kt * 64;
        __syncthreads();   // all warps done reading Ks/Vs (and Q STS at kt=0)

        // K transposed: Ks[d][key]
        #pragma unroll
        for (int i = 0; i < 4; i++) {
            int d = kg * 16 + i * 4;
            float4 k4 = *(const float4*)&Kbase[(size_t)(kb + kr) * D_MODEL + d];
            Ks[(d + 0) * FK_STR + kr] = f2tf(k4.x);
            Ks[(d + 1) * FK_STR + kr] = f2tf(k4.y);
            Ks[(d + 2) * FK_STR + kr] = f2tf(k4.z);
            Ks[(d + 3) * FK_STR + kr] = f2tf(k4.w);
        }
        // V natural: Vs[key][d]
        #pragma unroll
        for (int c = 0; c < 4; c++) {
            int r = lr + c * 16;
            float4 v4 = *(const float4*)&Vbase[(size_t)(kb + r) * D_MODEL + ld4];
            uint4 u = make_uint4(f2tf(v4.x), f2tf(v4.y), f2tf(v4.z), f2tf(v4.w));
            *(uint4*)&Vsm[r * FK_STR + ld4] = u;
        }
        __syncthreads();

        // ---- S = Q @ K^T (warp: 16 rows x 64 keys) ----
        float s[8][4];
        #pragma unroll
        for (int nt = 0; nt < 8; nt++)
            #pragma unroll
            for (int i = 0; i < 4; i++) s[nt][i] = 0.f;

        #pragma unroll
        for (int k8 = 0; k8 < 8; k8++) {
            int kc = k8 * 8 + lr4;
            unsigned a[4];
            a[0] = Qs[rw * FQ_STR + kc];
            a[1] = Qs[(rw + 8) * FQ_STR + kc];
            a[2] = Qs[rw * FQ_STR + kc + 4];
            a[3] = Qs[(rw + 8) * FQ_STR + kc + 4];
            #pragma unroll
            for (int nt = 0; nt < 8; nt++) {
                unsigned b0 = Ks[kc * FK_STR + nt * 8 + lq];
                unsigned b1 = Ks[(kc + 4) * FK_STR + nt * 8 + lq];
                mma_tf32(s[nt], a, b0, b1);
            }
        }

        // ---- causal mask (only last two key tiles can clip) ----
        if (kt >= 2 * qt) {
            int row0 = qb + rw;
            #pragma unroll
            for (int nt = 0; nt < 8; nt++) {
                int c0 = kb + nt * 8 + 2 * lr4;
                if (c0 > row0)     s[nt][0] = -FLT_MAX;
                if (c0 + 1 > row0) s[nt][1] = -FLT_MAX;
                if (c0 > row0 + 8)     s[nt][2] = -FLT_MAX;
                if (c0 + 1 > row0 + 8) s[nt][3] = -FLT_MAX;
            }
        }

        // ---- online softmax, fully in registers ----
        {
            float a0 = -FLT_MAX, a1 = -FLT_MAX;
            #pragma unroll
            for (int nt = 0; nt < 8; nt++) {
                a0 = fmaxf(a0, fmaxf(s[nt][0], s[nt][1]));
                a1 = fmaxf(a1, fmaxf(s[nt][2], s[nt][3]));
            }
            a0 = fmaxf(a0, __shfl_xor_sync(0xffffffffu, a0, 1));
            a0 = fmaxf(a0, __shfl_xor_sync(0xffffffffu, a0, 2));
            a1 = fmaxf(a1, __shfl_xor_sync(0xffffffffu, a1, 1));
            a1 = fmaxf(a1, __shfl_xor_sync(0xffffffffu, a1, 2));
            float mn0 = fmaxf(m0, a0), mn1 = fmaxf(m1, a1);
            float c0 = __expf(m0 - mn0), c1 = __expf(m1 - mn1);
            float sum0 = 0.f, sum1 = 0.f;
            #pragma unroll
            for (int nt = 0; nt < 8; nt++) {
                float p0 = __expf(s[nt][0] - mn0);
                float p1 = __expf(s[nt][1] - mn0);
                float p2 = __expf(s[nt][2] - mn1);
                float p3 = __expf(s[nt][3] - mn1);
                sum0 += p0 + p1;
                sum1 += p2 + p3;
                s[nt][0] = __uint_as_float(f2tf(p0));
                s[nt][1] = __uint_as_float(f2tf(p1));
                s[nt][2] = __uint_as_float(f2tf(p2));
                s[nt][3] = __uint_as_float(f2tf(p3));
            }
            sum0 += __shfl_xor_sync(0xffffffffu, sum0, 1);
            sum0 += __shfl_xor_sync(0xffffffffu, sum0, 2);
            sum1 += __shfl_xor_sync(0xffffffffu, sum1, 1);
            sum1 += __shfl_xor_sync(0xffffffffu, sum1, 2);
            l0 = l0 * c0 + sum0;
            l1 = l1 * c1 + sum1;
            m0 = mn0; m1 = mn1;
            #pragma unroll
            for (int nt = 0; nt < 8; nt++) {
                o[nt][0] *= c0; o[nt][1] *= c0;
                o[nt][2] *= c1; o[nt][3] *= c1;
            }
        }

        // ---- P -> warp-private smem (A-fragment relayout) ----
        #pragma unroll
        for (int nt = 0; nt < 8; nt++) {
            int col = nt * 8 + 2 * lr4;
            *(float2*)&Ps[rw * FQ_STR + col] = make_float2(s[nt][0], s[nt][1]);
            *(float2*)&Ps[(rw + 8) * FQ_STR + col] = make_float2(s[nt][2], s[nt][3]);
        }
        __syncwarp();

        // ---- O += P @ V ----
        #pragma unroll
        for (int k8 = 0; k8 < 8; k8++) {
            int kc = k8 * 8 + lr4;
            unsigned a[4];
            a[0] = Ps[rw * FQ_STR + kc];
            a[1] = Ps[(rw + 8) * FQ_STR + kc];
            a[2] = Ps[rw * FQ_STR + kc + 4];
            a[3] = Ps[(rw + 8) * FQ_STR + kc + 4];
            #pragma unroll
            for (int nt = 0; nt < 8; nt++) {
                unsigned b0 = Vsm[kc * FK_STR + nt * 8 + lq];
                unsigned b1 = Vsm[(kc + 4) * FK_STR + nt * 8 + lq];
                mma_tf32(o[nt], a, b0, b1);
            }
        }
    }

    // ---- normalize + write O (all state in registers) ----
    {
        float inv0 = 1.0f / l0;
        float inv1 = 1.0f / l1;
        int r0 = qb + rw;
        #pragma unroll
        for (int nt = 0; nt < 8; nt++) {
            int col = nt * 8 + 2 * lr4;
            *(float2*)&Obase[(size_t)r0 * D_MODEL + col] =
                make_float2(o[nt][0] * inv0, o[nt][1] * inv0);
            *(float2*)&Obase[(size_t)(r0 + 8) * D_MODEL + col] =
                make_float2(o[nt][2] * inv1, o[nt][3] * inv1);
        }
    }
}

// ---------------------------------------------------------------------------
// Host launcher
// ---------------------------------------------------------------------------
extern "C" void kernel_launch(void* const* d_in, const int* in_sizes, int n_in,
                              void* d_out, int out_size)
{
    const float* x  = (const float*)d_in[0];
    const float* wq = (const float*)d_in[1];
    const float* bq = (const float*)d_in[2];
    const float* wk = (const float*)d_in[3];
    const float* bk = (const float*)d_in[4];
    const float* wv = (const float*)d_in[5];
    const float* bv = (const float*)d_in[6];
    const float* wo = (const float*)d_in[7];
    const float* bo = (const float*)d_in[8];
    float* out = (float*)d_out;

    int M = in_sizes[0] / D_MODEL;   // B*S = 8192

    float *q, *k, *v, *attn;
    cudaGetSymbolAddress((void**)&q,    g_q);
    cudaGetSymbolAddress((void**)&k,    g_k);
    cudaGetSymbolAddress((void**)&v,    g_v);
    cudaGetSymbolAddress((void**)&attn, g_attn);

    cudaFuncSetAttribute(flash_attn_tc,
                         cudaFuncAttributeMaxDynamicSharedMemorySize, FA_SMEM);

    dim3 gblk(512);

    // Fused QKV projections (z selects weight/bias/output)
    dim3 ggrd3(D_MODEL / 128, M / 128, 3);
    gemm_tc<<<ggrd3, gblk>>>(x, wq, wk, wv, bq, bk, bv, q, k, v,
                             M, D_MODEL, D_MODEL);

    dim3 fgrd(BATCH * NUM_HEADS, SEQ / 128);
    flash_attn_tc<<<fgrd, 256, FA_SMEM>>>(q, k, v, attn);

    // Output projection (single operand set)
    dim3 ggrd1(D_MODEL / 128, M / 128, 1);
    gemm_tc<<<ggrd1, gblk>>>(attn, wo, wo, wo, bo, bo, bo, out, out, out,
                             M, D_MODEL, D_MODEL);
}

// round 13
// speedup vs baseline: 1.4378x; 1.4378x over previous
#include <cuda_runtime.h>
#include <math.h>
#include <float.h>

#define D_MODEL 1024
#define NUM_HEADS 16
#define D_K 64
#define SEQ 2048
#define BATCH 4

// Scratch (static device globals -- no runtime allocation allowed)
__device__ float g_q[BATCH * SEQ * D_MODEL];
__device__ float g_k[BATCH * SEQ * D_MODEL];
__device__ float g_v[BATCH * SEQ * D_MODEL];
__device__ float g_attn[BATCH * SEQ * D_MODEL];

// ---------------------------------------------------------------------------
// tf32 helpers
// ---------------------------------------------------------------------------
__device__ __forceinline__ unsigned f2tf(float x) {
    unsigned u;
    asm("cvt.rna.tf32.f32 %0, %1;" : "=r"(u) : "f"(x));
    return u;
}

__device__ __forceinline__ void mma_tf32(float c[4], const unsigned a[4],
                                         unsigned b0, unsigned b1) {
    asm volatile(
        "mma.sync.aligned.m16n8k8.row.col.f32.tf32.tf32.f32 "
        "{%0,%1,%2,%3}, {%4,%5,%6,%7}, {%8,%9}, {%0,%1,%2,%3};\n"
        : "+f"(c[0]), "+f"(c[1]), "+f"(c[2]), "+f"(c[3])
        : "r"(a[0]), "r"(a[1]), "r"(a[2]), "r"(a[3]), "r"(b0), "r"(b1));
}

// ---------------------------------------------------------------------------
// TF32 tensor-core GEMM with fused bias (R9-proven, frozen).
// C[M,N] = A[M,K] @ Bz[K,N] + biasz[N], operand set selected by blockIdx.z.
// BM=128, BN=128, BK=32. 256 threads = 8 warps (2m x 4n), warp tile 64x32.
// As: m-major [128][36]; Bs: k-major [32][136]; conflict-free frag loads.
// cvt.rna at global->smem store time (1x per element).
// ---------------------------------------------------------------------------
#define GA_STR 36
#define GB_STR 136

__global__ __launch_bounds__(256) void gemm_tc(
    const float* __restrict__ A,
    const float* __restrict__ B0, const float* __restrict__ B1,
    const float* __restrict__ B2,
    const float* __restrict__ bias0, const float* __restrict__ bias1,
    const float* __restrict__ bias2,
    float* __restrict__ C0, float* __restrict__ C1, float* __restrict__ C2,
    int M, int N, int K)
{
    __shared__ unsigned As[128 * GA_STR];
    __shared__ unsigned Bs[32 * GB_STR];

    int z = blockIdx.z;
    const float* B    = (z == 0) ? B0    : (z == 1) ? B1    : B2;
    const float* bias = (z == 0) ? bias0 : (z == 1) ? bias1 : bias2;
    float*       C    = (z == 0) ? C0    : (z == 1) ? C1    : C2;

    int t    = threadIdx.x;
    int lane = t & 31;
    int w    = t >> 5;
    int wm   = w >> 2;         // 0..1
    int wn   = w & 3;          // 0..3
    int bm   = blockIdx.y * 128;
    int bn   = blockIdx.x * 128;
    int lq   = lane >> 2;      // 0..7
    int lr4  = lane & 3;       // 0..3

    float acc[4][4][4];
    #pragma unroll
    for (int mt = 0; mt < 4; mt++)
        #pragma unroll
        for (int nt = 0; nt < 4; nt++)
            #pragma unroll
            for (int i = 0; i < 4; i++) acc[mt][nt][i] = 0.f;

    for (int kb = 0; kb < K; kb += 32) {
        // load A tile 128x32
        #pragma unroll
        for (int i = 0; i < 4; i++) {
            int idx = t + i * 256;
            int m = idx >> 3, kc = idx & 7;
            float4 a4 = *(const float4*)&A[(size_t)(bm + m) * K + kb + kc * 4];
            uint4 u = make_uint4(f2tf(a4.x), f2tf(a4.y), f2tf(a4.z), f2tf(a4.w));
            *(uint4*)&As[m * GA_STR + kc * 4] = u;
        }
        // load B tile 32x128
        #pragma unroll
        for (int i = 0; i < 4; i++) {
            int idx = t + i * 256;
            int r = idx >> 5, c = idx & 31;
            float4 b4 = *(const float4*)&B[(size_t)(kb + r) * N + bn + c * 4];
            uint4 u = make_uint4(f2tf(b4.x), f2tf(b4.y), f2tf(b4.z), f2tf(b4.w));
            *(uint4*)&Bs[r * GB_STR + c * 4] = u;
        }
        __syncthreads();

        #pragma unroll
        for (int k8 = 0; k8 < 4; k8++) {
            int kc = k8 * 8 + lr4;
            unsigned a[4][4];
            #pragma unroll
            for (int mt = 0; mt < 4; mt++) {
                int mr = wm * 64 + mt * 16 + lq;
                a[mt][0] = As[mr * GA_STR + kc];
                a[mt][1] = As[(mr + 8) * GA_STR + kc];
                a[mt][2] = As[mr * GA_STR + kc + 4];
                a[mt][3] = As[(mr + 8) * GA_STR + kc + 4];
            }
            unsigned b[4][2];
            #pragma unroll
            for (int nt = 0; nt < 4; nt++) {
                int nc = wn * 32 + nt * 8 + lq;
                b[nt][0] = Bs[kc * GB_STR + nc];
                b[nt][1] = Bs[(kc + 4) * GB_STR + nc];
            }
            #pragma unroll
            for (int mt = 0; mt < 4; mt++)
                #pragma unroll
                for (int nt = 0; nt < 4; nt++)
                    mma_tf32(acc[mt][nt], a[mt], b[nt][0], b[nt][1]);
        }
        __syncthreads();
    }

    // epilogue
    #pragma unroll
    for (int nt = 0; nt < 4; nt++) {
        int col = bn + wn * 32 + nt * 8 + 2 * lr4;
        float2 bi = *(const float2*)&bias[col];
        #pragma unroll
        for (int mt = 0; mt < 4; mt++) {
            int r0 = bm + wm * 64 + mt * 16 + lq;
            float2 o0 = make_float2(acc[mt][nt][0] + bi.x, acc[mt][nt][1] + bi.y);
            float2 o1 = make_float2(acc[mt][nt][2] + bi.x, acc[mt][nt][3] + bi.y);
            *(float2*)&C[(size_t)r0 * N + col] = o0;
            *(float2*)&C[(size_t)(r0 + 8) * N + col] = o1;
        }
    }
}

// ---------------------------------------------------------------------------
// TF32 tensor-core causal flash attention, 128q x 64k tiles.
// 256 threads = 8 warps; warp w owns rows w*16..w*16+15 and ALL 64 keys.
//
// KEY PERMUTATION: the K tile's B-fragments are loaded with keys permuted
// within each 8-key group by kappa(j) = (j&1) ? j/2+4 : j/2 so that the
// S-MMA output registers land directly in PV A-fragment order:
//   s[nt][0] = P[rw  ][key nt*8+lr4]     -> PV a[0]
//   s[nt][1] = P[rw  ][key nt*8+lr4+4]   -> PV a[2]
//   s[nt][2] = P[rw+8][key nt*8+lr4]     -> PV a[1]
//   s[nt][3] = P[rw+8][key nt*8+lr4+4]   -> PV a[3]
// Softmax is key-order invariant; causal mask uses the permuted key indices.
// V stays naturally ordered (PV k-index = true key index). P never touches
// smem -- the Ps buffer, 16 STS, 32 LDS and syncwarp per iter are deleted.
// Smem (floats): Qs[128][68], Ks[64][72] (d-major), Vs[64][72].
// ---------------------------------------------------------------------------
#define FQ_STR 68
#define FK_STR 72
#define FA_SMEM ((128 * FQ_STR + 64 * FK_STR * 2) * 4)

__global__ __launch_bounds__(256, 2) void flash_attn_tc(
    const float* __restrict__ Q, const float* __restrict__ K,
    const float* __restrict__ V, float* __restrict__ O)
{
    extern __shared__ unsigned usm[];
    unsigned* Qs  = usm;                         // 128*68  (tf32, pre-scaled)
    unsigned* Ks  = Qs + 128 * FQ_STR;           // 64*72   [d][key]
    unsigned* Vsm = Ks + 64 * FK_STR;            // 64*72   [key][d]

    int bh = blockIdx.x;                  // 0..63
    int qt = 15 - blockIdx.y;             // long blocks first
    int b  = bh >> 4;
    int h  = bh & 15;
    int qb = qt * 128;

    const float* Qbase = Q + (size_t)b * SEQ * D_MODEL + h * D_K;
    const float* Kbase = K + (size_t)b * SEQ * D_MODEL + h * D_K;
    const float* Vbase = V + (size_t)b * SEQ * D_MODEL + h * D_K;
    float*       Obase = O + (size_t)b * SEQ * D_MODEL + h * D_K;

    int t    = threadIdx.x;
    int lane = t & 31;
    int w    = t >> 5;         // warp 0..7 -> rows w*16..+15
    int lq   = lane >> 2;      // 0..7
    int lr4  = lane & 3;       // 0..3
    int rw   = w * 16 + lq;    // warp-local row (first half)
    // permuted B-fragment key index within each 8-key group
    int pl   = (lq & 1) ? (lq >> 1) + 4 : (lq >> 1);

    // ---- load Q tile (128x64) as tf32, scale folded ----
    {
        int lr  = t >> 4;          // 0..15
        int ld4 = (t & 15) * 4;
        #pragma unroll
        for (int c = 0; c < 8; c++) {
            int r = lr + c * 16;
            float4 q4 = *(const float4*)&Qbase[(size_t)(qb + r) * D_MODEL + ld4];
            uint4 u = make_uint4(f2tf(q4.x * 0.125f), f2tf(q4.y * 0.125f),
                                 f2tf(q4.z * 0.125f), f2tf(q4.w * 0.125f));
            *(uint4*)&Qs[r * FQ_STR + ld4] = u;
        }
    }

    float o[8][4];
    #pragma unroll
    for (int nt = 0; nt < 8; nt++)
        #pragma unroll
        for (int i = 0; i < 4; i++) o[nt][i] = 0.f;

    float m0 = -FLT_MAX, m1 = -FLT_MAX, l0 = 0.f, l1 = 0.f;

    int kr = t & 63;           // K loader: row 0..63
    int kg = t >> 6;           // d-group 0..3
    int lr = t >> 4;           // V loader row base
    int ld4 = (t & 15) * 4;

    int nkt = 2 * qt + 2;
    for (int kt = 0; kt < nkt; kt++) {
        int kb = kt * 64;
        __syncthreads();   // all warps done reading Ks/Vs (and Q STS at kt=0)

        // K transposed: Ks[d][key]
        #pragma unroll
        for (int i = 0; i < 4; i++) {
            int d = kg * 16 + i * 4;
            float4 k4 = *(const float4*)&Kbase[(size_t)(kb + kr) * D_MODEL + d];
            Ks[(d + 0) * FK_STR + kr] = f2tf(k4.x);
            Ks[(d + 1) * FK_STR + kr] = f2tf(k4.y);
            Ks[(d + 2) * FK_STR + kr] = f2tf(k4.z);
            Ks[(d + 3) * FK_STR + kr] = f2tf(k4.w);
        }
        // V natural: Vs[key][d]
        #pragma unroll
        for (int c = 0; c < 4; c++) {
            int r = lr + c * 16;
            float4 v4 = *(const float4*)&Vbase[(size_t)(kb + r) * D_MODEL + ld4];
            uint4 u = make_uint4(f2tf(v4.x), f2tf(v4.y), f2tf(v4.z), f2tf(v4.w));
            *(uint4*)&Vsm[r * FK_STR + ld4] = u;
        }
        __syncthreads();

        // ---- S = Q @ K^T with permuted B keys ----
        float s[8][4];
        #pragma unroll
        for (int nt = 0; nt < 8; nt++)
            #pragma unroll
            for (int i = 0; i < 4; i++) s[nt][i] = 0.f;

        #pragma unroll
        for (int k8 = 0; k8 < 8; k8++) {
            int kc = k8 * 8 + lr4;
            unsigned a[4];
            a[0] = Qs[rw * FQ_STR + kc];
            a[1] = Qs[(rw + 8) * FQ_STR + kc];
            a[2] = Qs[rw * FQ_STR + kc + 4];
            a[3] = Qs[(rw + 8) * FQ_STR + kc + 4];
            #pragma unroll
            for (int nt = 0; nt < 8; nt++) {
                unsigned b0 = Ks[kc * FK_STR + nt * 8 + pl];
                unsigned b1 = Ks[(kc + 4) * FK_STR + nt * 8 + pl];
                mma_tf32(s[nt], a, b0, b1);
            }
        }

        // ---- causal mask on permuted keys (only last two key tiles clip) ----
        // s[nt][0],s[nt][2] <-> key kb+nt*8+lr4 ; s[nt][1],s[nt][3] <-> +4
        if (kt >= 2 * qt) {
            int row0 = qb + rw;
            #pragma unroll
            for (int nt = 0; nt < 8; nt++) {
                int key0 = kb + nt * 8 + lr4;
                int key1 = key0 + 4;
                if (key0 > row0)     s[nt][0] = -FLT_MAX;
                if (key1 > row0)     s[nt][1] = -FLT_MAX;
                if (key0 > row0 + 8) s[nt][2] = -FLT_MAX;
                if (key1 > row0 + 8) s[nt][3] = -FLT_MAX;
            }
        }

        // ---- online softmax, fully in registers (order-invariant) ----
        {
            float a0 = -FLT_MAX, a1 = -FLT_MAX;
            #pragma unroll
            for (int nt = 0; nt < 8; nt++) {
                a0 = fmaxf(a0, fmaxf(s[nt][0], s[nt][1]));
                a1 = fmaxf(a1, fmaxf(s[nt][2], s[nt][3]));
            }
            a0 = fmaxf(a0, __shfl_xor_sync(0xffffffffu, a0, 1));
            a0 = fmaxf(a0, __shfl_xor_sync(0xffffffffu, a0, 2));
            a1 = fmaxf(a1, __shfl_xor_sync(0xffffffffu, a1, 1));
            a1 = fmaxf(a1, __shfl_xor_sync(0xffffffffu, a1, 2));
            float mn0 = fmaxf(m0, a0), mn1 = fmaxf(m1, a1);
            float c0 = __expf(m0 - mn0), c1 = __expf(m1 - mn1);
            float sum0 = 0.f, sum1 = 0.f;
            #pragma unroll
            for (int nt = 0; nt < 8; nt++) {
                float p0 = __expf(s[nt][0] - mn0);
                float p1 = __expf(s[nt][1] - mn0);
                float p2 = __expf(s[nt][2] - mn1);
                float p3 = __expf(s[nt][3] - mn1);
                sum0 += p0 + p1;
                sum1 += p2 + p3;
                s[nt][0] = __uint_as_float(f2tf(p0));
                s[nt][1] = __uint_as_float(f2tf(p1));
                s[nt][2] = __uint_as_float(f2tf(p2));
                s[nt][3] = __uint_as_float(f2tf(p3));
            }
            sum0 += __shfl_xor_sync(0xffffffffu, sum0, 1);
            sum0 += __shfl_xor_sync(0xffffffffu, sum0, 2);
            sum1 += __shfl_xor_sync(0xffffffffu, sum1, 1);
            sum1 += __shfl_xor_sync(0xffffffffu, sum1, 2);
            l0 = l0 * c0 + sum0;
            l1 = l1 * c1 + sum1;
            m0 = mn0; m1 = mn1;
            #pragma unroll
            for (int nt = 0; nt < 8; nt++) {
                o[nt][0] *= c0; o[nt][1] *= c0;
                o[nt][2] *= c1; o[nt][3] *= c1;
            }
        }

        // ---- O += P @ V : A-fragment taken DIRECTLY from s registers ----
        #pragma unroll
        for (int k8 = 0; k8 < 8; k8++) {
            int kc = k8 * 8 + lr4;
            unsigned a[4];
            a[0] = __float_as_uint(s[k8][0]);   // row rw,   k = kc
            a[1] = __float_as_uint(s[k8][2]);   // row rw+8, k = kc
            a[2] = __float_as_uint(s[k8][1]);   // row rw,   k = kc+4
            a[3] = __float_as_uint(s[k8][3]);   // row rw+8, k = kc+4
            #pragma unroll
            for (int nt = 0; nt < 8; nt++) {
                unsigned b0 = Vsm[kc * FK_STR + nt * 8 + lq];
                unsigned b1 = Vsm[(kc + 4) * FK_STR + nt * 8 + lq];
                mma_tf32(o[nt], a, b0, b1);
            }
        }
    }

    // ---- normalize + write O (all state in registers) ----
    {
        float inv0 = 1.0f / l0;
        float inv1 = 1.0f / l1;
        int r0 = qb + rw;
        #pragma unroll
        for (int nt = 0; nt < 8; nt++) {
            int col = nt * 8 + 2 * lr4;
            *(float2*)&Obase[(size_t)r0 * D_MODEL + col] =
                make_float2(o[nt][0] * inv0, o[nt][1] * inv0);
            *(float2*)&Obase[(size_t)(r0 + 8) * D_MODEL + col] =
                make_float2(o[nt][2] * inv1, o[nt][3] * inv1);
        }
    }
}

// ---------------------------------------------------------------------------
// Host launcher
// ---------------------------------------------------------------------------
extern "C" void kernel_launch(void* const* d_in, const int* in_sizes, int n_in,
                              void* d_out, int out_size)
{
    const float* x  = (const float*)d_in[0];
    const float* wq = (const float*)d_in[1];
    const float* bq = (const float*)d_in[2];
    const float* wk = (const float*)d_in[3];
    const float* bk = (const float*)d_in[4];
    const float* wv = (const float*)d_in[5];
    const float* bv = (const float*)d_in[6];
    const float* wo = (const float*)d_in[7];
    const float* bo = (const float*)d_in[8];
    float* out = (float*)d_out;

    int M = in_sizes[0] / D_MODEL;   // B*S = 8192

    float *q, *k, *v, *attn;
    cudaGetSymbolAddress((void**)&q,    g_q);
    cudaGetSymbolAddress((void**)&k,    g_k);
    cudaGetSymbolAddress((void**)&v,    g_v);
    cudaGetSymbolAddress((void**)&attn, g_attn);

    cudaFuncSetAttribute(flash_attn_tc,
                         cudaFuncAttributeMaxDynamicSharedMemorySize, FA_SMEM);

    dim3 gblk(256);

    // Fused QKV projections (z selects weight/bias/output)
    dim3 ggrd3(D_MODEL / 128, M / 128, 3);
    gemm_tc<<<ggrd3, gblk>>>(x, wq, wk, wv, bq, bk, bv, q, k, v,
                             M, D_MODEL, D_MODEL);

    dim3 fgrd(BATCH * NUM_HEADS, SEQ / 128);
    flash_attn_tc<<<fgrd, 256, FA_SMEM>>>(q, k, v, attn);

    // Output projection (single operand set)
    dim3 ggrd1(D_MODEL / 128, M / 128, 1);
    gemm_tc<<<ggrd1, gblk>>>(attn, wo, wo, wo, bo, bo, bo, out, out, out,
                             M, D_MODEL, D_MODEL);
}